// round 1
// baseline (speedup 1.0000x reference)
#include <cuda_runtime.h>
#include <cstdint>

#define S_LEN 2048
#define DMODEL 1024
#define NHEAD 16
#define DHEAD 64
#define BATCH 2
#define NROWS (BATCH * S_LEN)  // 4096

// Head-split scratch: [b][h][s][dh], 16 MB each (static device arrays: allowed).
__device__ float g_Q[BATCH * NHEAD * S_LEN * DHEAD];
__device__ float g_K[BATCH * NHEAD * S_LEN * DHEAD];
__device__ float g_V[BATCH * NHEAD * S_LEN * DHEAD];

__device__ __forceinline__ float fast_exp2(float x) {
    float y;
    asm("ex2.approx.ftz.f32 %0, %1;" : "=f"(y) : "f"(x));
    return y;
}

// ---------------------------------------------------------------------------
// Fused QKV projection: Y = X @ W^T + b, written head-split.
// z = blockIdx.z selects (q,Wq,bq)->g_Q (scaled), (k,..)->g_K, (v,..)->g_V.
// 128x128 block tile, BK=8, 256 threads, 8x8 per thread (split 4+4 pattern).
// ---------------------------------------------------------------------------
__global__ __launch_bounds__(256) void proj_kernel(
    const float* __restrict__ xq, const float* __restrict__ xk, const float* __restrict__ xv,
    const float* __restrict__ wq, const float* __restrict__ wk, const float* __restrict__ wv,
    const float* __restrict__ bq, const float* __restrict__ bk, const float* __restrict__ bv,
    const float* __restrict__ inv_scale)
{
    const int z = blockIdx.z;
    const float* __restrict__ X  = (z == 0) ? xq : (z == 1) ? xk : xv;
    const float* __restrict__ W  = (z == 0) ? wq : (z == 1) ? wk : wv;
    const float* __restrict__ Bp = (z == 0) ? bq : (z == 1) ? bk : bv;
    float* __restrict__ OUT = (z == 0) ? g_Q : (z == 1) ? g_K : g_V;
    // Fold 1/sqrt(Dh)=1/8, 1/inv_scale, and log2(e) (for exp2-domain softmax) into Q.
    const float scale = (z == 0) ? (0.125f * 1.44269504088896340736f / inv_scale[0]) : 1.0f;

    __shared__ float As[8][132];   // K-major, padded stride 132: conflict-free
    __shared__ float Bs[8][132];

    const int tid = threadIdx.x;
    const int tx = tid & 15;
    const int ty = tid >> 4;
    const int row0 = blockIdx.y * 128;
    const int col0 = blockIdx.x * 128;

    const int lr = tid >> 1;        // 0..127 : tile row loaded by this thread
    const int lk = (tid & 1) * 4;   // 0 or 4 : k sub-offset

    float acc[8][8];
#pragma unroll
    for (int i = 0; i < 8; i++)
#pragma unroll
        for (int j = 0; j < 8; j++) acc[i][j] = 0.0f;

    const float* Xp = X + (size_t)(row0 + lr) * DMODEL + lk;
    const float* Wp = W + (size_t)(col0 + lr) * DMODEL + lk;

    for (int kt = 0; kt < DMODEL; kt += 8) {
        const float4 a = *(const float4*)(Xp + kt);
        const float4 b = *(const float4*)(Wp + kt);
        __syncthreads();
        As[lk + 0][lr] = a.x; As[lk + 1][lr] = a.y; As[lk + 2][lr] = a.z; As[lk + 3][lr] = a.w;
        Bs[lk + 0][lr] = b.x; Bs[lk + 1][lr] = b.y; Bs[lk + 2][lr] = b.z; Bs[lk + 3][lr] = b.w;
        __syncthreads();
#pragma unroll
        for (int k = 0; k < 8; k++) {
            const float4 a0 = *(const float4*)&As[k][ty * 4];
            const float4 a1 = *(const float4*)&As[k][64 + ty * 4];
            const float4 b0 = *(const float4*)&Bs[k][tx * 4];
            const float4 b1 = *(const float4*)&Bs[k][64 + tx * 4];
            const float av[8] = {a0.x, a0.y, a0.z, a0.w, a1.x, a1.y, a1.z, a1.w};
            const float bv2[8] = {b0.x, b0.y, b0.z, b0.w, b1.x, b1.y, b1.z, b1.w};
#pragma unroll
            for (int i = 0; i < 8; i++)
#pragma unroll
                for (int j = 0; j < 8; j++)
                    acc[i][j] = fmaf(av[i], bv2[j], acc[i][j]);
        }
    }

    // Epilogue: add bias, scale, write head-split [b][h][s][dh] (float4 stores).
    const float4 bias0 = *(const float4*)(Bp + col0 + tx * 4);
    const float4 bias1 = *(const float4*)(Bp + col0 + 64 + tx * 4);
    const float bb[8] = {bias0.x, bias0.y, bias0.z, bias0.w,
                         bias1.x, bias1.y, bias1.z, bias1.w};
#pragma unroll
    for (int i = 0; i < 8; i++) {
        const int rloc = (i < 4) ? (ty * 4 + i) : (64 + ty * 4 + (i - 4));
        const int r = row0 + rloc;
        const int b = r >> 11;            // / 2048
        const int s = r & (S_LEN - 1);
#pragma unroll
        for (int jg = 0; jg < 2; jg++) {
            const int e0 = col0 + jg * 64 + tx * 4;   // 4 consecutive e, same head
            const int h  = e0 >> 6;
            const int dh = e0 & 63;
            float4 o;
            o.x = (acc[i][jg * 4 + 0] + bb[jg * 4 + 0]) * scale;
            o.y = (acc[i][jg * 4 + 1] + bb[jg * 4 + 1]) * scale;
            o.z = (acc[i][jg * 4 + 2] + bb[jg * 4 + 2]) * scale;
            o.w = (acc[i][jg * 4 + 3] + bb[jg * 4 + 3]) * scale;
            *(float4*)&OUT[(((size_t)b * NHEAD + h) * S_LEN + s) * DHEAD + dh] = o;
        }
    }
}

// ---------------------------------------------------------------------------
// Flash attention, fp32. Grid: (qblock 0..31, bh 0..31). 256 threads.
// 64 q-rows x 64 keys per tile; online softmax in exp2 domain (log2e folded
// into Q at projection). Smem: Qs (d-major), KPs (K d-major, then recycled as
// P row-major after a sync), Vs (natural). 3*16KB = exactly 48KB static.
// ---------------------------------------------------------------------------
__global__ __launch_bounds__(256) void attn_kernel(float* __restrict__ out)
{
    __shared__ float Qs[64][64];    // Qs[d][r]
    __shared__ float KPs[64][64];   // K phase: [d][c] ; P phase: [r][k]
    __shared__ float Vs[64][64];    // Vs[k][dh]

    const int tid = threadIdx.x;
    const int tx = tid & 15;
    const int ty = tid >> 4;
    const int bh = blockIdx.y;      // b*16 + h
    const int qb = blockIdx.x;

    const float* __restrict__ Qg = g_Q + (size_t)bh * S_LEN * DHEAD + (size_t)qb * 64 * DHEAD;
    const float* __restrict__ Kg = g_K + (size_t)bh * S_LEN * DHEAD;
    const float* __restrict__ Vg = g_V + (size_t)bh * S_LEN * DHEAD;

    const int lrow = tid >> 2;          // 0..63
    const int ldg  = (tid & 3) * 4;     // 0,4,8,12

    // Load Q tile transposed into Qs[d][r]
#pragma unroll
    for (int p = 0; p < 4; p++) {
        const int d = ldg + p * 16;
        const float4 v = *(const float4*)(Qg + lrow * DHEAD + d);
        Qs[d + 0][lrow] = v.x; Qs[d + 1][lrow] = v.y;
        Qs[d + 2][lrow] = v.z; Qs[d + 3][lrow] = v.w;
    }

    float m[4], l[4], o[4][4];
#pragma unroll
    for (int i = 0; i < 4; i++) {
        m[i] = -1e30f;
        l[i] = 0.0f;
#pragma unroll
        for (int j = 0; j < 4; j++) o[i][j] = 0.0f;
    }

    for (int kt = 0; kt < S_LEN; kt += 64) {
        __syncthreads();   // prev PV done with KPs(P)/Vs ; also covers Q-load on iter 0

        // Load K tile (transposed) and V tile (natural)
#pragma unroll
        for (int p = 0; p < 4; p++) {
            const int d = ldg + p * 16;
            const float4 kv = *(const float4*)(Kg + (size_t)(kt + lrow) * DHEAD + d);
            KPs[d + 0][lrow] = kv.x; KPs[d + 1][lrow] = kv.y;
            KPs[d + 2][lrow] = kv.z; KPs[d + 3][lrow] = kv.w;
            const float4 vv = *(const float4*)(Vg + (size_t)(kt + lrow) * DHEAD + d);
            *(float4*)&Vs[lrow][d] = vv;
        }
        __syncthreads();

        // S = Q K^T  (scores already in log2 domain via folded scale)
        float s[4][4];
#pragma unroll
        for (int i = 0; i < 4; i++)
#pragma unroll
            for (int j = 0; j < 4; j++) s[i][j] = 0.0f;

#pragma unroll 8
        for (int d = 0; d < 64; d++) {
            const float4 qv = *(const float4*)&Qs[d][ty * 4];
            const float4 kv = *(const float4*)&KPs[d][tx * 4];
            const float qa[4] = {qv.x, qv.y, qv.z, qv.w};
            const float ka[4] = {kv.x, kv.y, kv.z, kv.w};
#pragma unroll
            for (int i = 0; i < 4; i++)
#pragma unroll
                for (int j = 0; j < 4; j++)
                    s[i][j] = fmaf(qa[i], ka[j], s[i][j]);
        }

        // Online softmax (row stats across 16 lanes of tx)
        float mx[4];
#pragma unroll
        for (int i = 0; i < 4; i++)
            mx[i] = fmaxf(fmaxf(s[i][0], s[i][1]), fmaxf(s[i][2], s[i][3]));
#pragma unroll
        for (int off = 1; off < 16; off <<= 1)
#pragma unroll
            for (int i = 0; i < 4; i++)
                mx[i] = fmaxf(mx[i], __shfl_xor_sync(0xffffffffu, mx[i], off));

        float corr[4];
#pragma unroll
        for (int i = 0; i < 4; i++) {
            const float mn = fmaxf(m[i], mx[i]);
            corr[i] = fast_exp2(m[i] - mn);
            m[i] = mn;
        }

        float rs[4];
#pragma unroll
        for (int i = 0; i < 4; i++) {
            float r = 0.0f;
#pragma unroll
            for (int j = 0; j < 4; j++) {
                s[i][j] = fast_exp2(s[i][j] - m[i]);
                r += s[i][j];
            }
            rs[i] = r;
        }
#pragma unroll
        for (int off = 1; off < 16; off <<= 1)
#pragma unroll
            for (int i = 0; i < 4; i++)
                rs[i] += __shfl_xor_sync(0xffffffffu, rs[i], off);

#pragma unroll
        for (int i = 0; i < 4; i++) {
            l[i] = l[i] * corr[i] + rs[i];
#pragma unroll
            for (int j = 0; j < 4; j++) o[i][j] *= corr[i];
        }

        __syncthreads();   // everyone finished reading KPs as K

        // Write P row-major into recycled KPs: P[r][k]
#pragma unroll
        for (int i = 0; i < 4; i++)
            *(float4*)&KPs[ty * 4 + i][tx * 4] =
                make_float4(s[i][0], s[i][1], s[i][2], s[i][3]);
        __syncthreads();

        // O += P V
#pragma unroll 4
        for (int k0 = 0; k0 < 64; k0 += 4) {
            float4 pv[4], vv[4];
#pragma unroll
            for (int i = 0; i < 4; i++) pv[i] = *(const float4*)&KPs[ty * 4 + i][k0];
#pragma unroll
            for (int c = 0; c < 4; c++) vv[c] = *(const float4*)&Vs[k0 + c][tx * 4];
#pragma unroll
            for (int i = 0; i < 4; i++) {
                const float pa[4] = {pv[i].x, pv[i].y, pv[i].z, pv[i].w};
#pragma unroll
                for (int c = 0; c < 4; c++) {
                    const float va[4] = {vv[c].x, vv[c].y, vv[c].z, vv[c].w};
#pragma unroll
                    for (int j = 0; j < 4; j++)
                        o[i][j] = fmaf(pa[c], va[j], o[i][j]);
                }
            }
        }
    }

    // Epilogue: out[b, (s*64+dh)*16 + h]
    const int b = bh >> 4;
    const int h = bh & 15;
    float* outb = out + (size_t)b * (S_LEN * DMODEL) + h;
#pragma unroll
    for (int i = 0; i < 4; i++) {
        const float inv_l = 1.0f / l[i];
        const int sg = qb * 64 + ty * 4 + i;
#pragma unroll
        for (int j = 0; j < 4; j++) {
            const int dh = tx * 4 + j;
            outb[(size_t)(sg * DHEAD + dh) * NHEAD] = o[i][j] * inv_l;
        }
    }
}

extern "C" void kernel_launch(void* const* d_in, const int* in_sizes, int n_in,
                              void* d_out, int out_size)
{
    (void)in_sizes; (void)n_in; (void)out_size;
    const float* q   = (const float*)d_in[0];
    const float* k   = (const float*)d_in[1];
    const float* v   = (const float*)d_in[2];
    // d_in[3] = mask (unused by the reference forward)
    const float* inv = (const float*)d_in[4];
    const float* Wq  = (const float*)d_in[5];
    const float* bq  = (const float*)d_in[6];
    const float* Wk  = (const float*)d_in[7];
    const float* bk  = (const float*)d_in[8];
    const float* Wv  = (const float*)d_in[9];
    const float* bv  = (const float*)d_in[10];

    dim3 gproj(DMODEL / 128, NROWS / 128, 3);   // (8, 32, 3)
    proj_kernel<<<gproj, 256>>>(q, k, v, Wq, Wk, Wv, bq, bk, bv, inv);

    dim3 gattn(S_LEN / 64, BATCH * NHEAD);      // (32, 32)
    attn_kernel<<<gattn, 256>>>((float*)d_out);
}

// round 3
// speedup vs baseline: 2.5648x; 2.5648x over previous
#include <cuda_runtime.h>
#include <cstdint>

#define S_LEN 2048
#define DMODEL 1024
#define NHEAD 16
#define DHEAD 64
#define BATCH 2
#define NROWS (BATCH * S_LEN)  // 4096

// Head-split scratch: [b][h][s][dh]
__device__ float g_Q[BATCH * NHEAD * S_LEN * DHEAD];
__device__ float g_K[BATCH * NHEAD * S_LEN * DHEAD];
__device__ float g_V[BATCH * NHEAD * S_LEN * DHEAD];

__device__ __forceinline__ float fast_exp2(float x) {
    float y;
    asm("ex2.approx.ftz.f32 %0, %1;" : "=f"(y) : "f"(x));
    return y;
}

// Round fp32 -> tf32 bit pattern (round-to-nearest; truncation would bias dot products)
__device__ __forceinline__ uint32_t f2tf(float x) {
    uint32_t u;
    asm("cvt.rna.tf32.f32 %0, %1;" : "=r"(u) : "f"(x));
    return u;
}
__device__ __forceinline__ float f2tf_f(float x) { return __uint_as_float(f2tf(x)); }

// D = A*B + D   (m16n8k8 tf32, row.col)
__device__ __forceinline__ void mma_tf32(float* d, const uint32_t* a, const uint32_t* b) {
    asm volatile(
        "mma.sync.aligned.m16n8k8.row.col.f32.tf32.tf32.f32 "
        "{%0,%1,%2,%3}, {%4,%5,%6,%7}, {%8,%9}, {%0,%1,%2,%3};\n"
        : "+f"(d[0]), "+f"(d[1]), "+f"(d[2]), "+f"(d[3])
        : "r"(a[0]), "r"(a[1]), "r"(a[2]), "r"(a[3]), "r"(b[0]), "r"(b[1]));
}

// ---------------------------------------------------------------------------
// Projection: Y = X @ W^T + b -> head-split [b][h][s][dh].
// 128x128 tile, BK=32, 256 threads (8 warps, warp = 64 rows x 32 cols).
// Operands staged in smem as tf32, ld=36 (36 % 32 == 4 -> conflict-free frags).
// ---------------------------------------------------------------------------
__global__ __launch_bounds__(256, 2) void proj_kernel(
    const float* __restrict__ xq, const float* __restrict__ xk, const float* __restrict__ xv,
    const float* __restrict__ wq, const float* __restrict__ wk, const float* __restrict__ wv,
    const float* __restrict__ bq, const float* __restrict__ bk, const float* __restrict__ bv,
    const float* __restrict__ inv_scale)
{
    const int z = blockIdx.z;
    const float* __restrict__ X  = (z == 0) ? xq : (z == 1) ? xk : xv;
    const float* __restrict__ W  = (z == 0) ? wq : (z == 1) ? wk : wv;
    const float* __restrict__ Bp = (z == 0) ? bq : (z == 1) ? bk : bv;
    float* __restrict__ OUT = (z == 0) ? g_Q : (z == 1) ? g_K : g_V;
    // Fold 1/sqrt(Dh)=1/8, 1/inv_scale, log2(e) into Q
    const float scale = (z == 0) ? (0.125f * 1.44269504088896340736f / inv_scale[0]) : 1.0f;

    __shared__ float Xs[128 * 36];
    __shared__ float Ws[128 * 36];
    __shared__ float bias_s[128];

    const int tid  = threadIdx.x;
    const int lane = tid & 31;
    const int wid  = tid >> 5;
    const int row0 = blockIdx.y * 128;
    const int col0 = blockIdx.x * 128;

    const int wr = (wid & 1) * 64;   // warp row origin
    const int wc = (wid >> 1) * 32;  // warp col origin

    if (tid < 128) bias_s[tid] = Bp[col0 + tid];

    float acc[4][4][4];
#pragma unroll
    for (int mt = 0; mt < 4; mt++)
#pragma unroll
        for (int nt = 0; nt < 4; nt++)
#pragma unroll
            for (int j = 0; j < 4; j++) acc[mt][nt][j] = 0.0f;

    const int lr = tid >> 3;          // 0..31 (row group)
    const int lk = (tid & 7) * 4;     // 0..28 (k quad)

    for (int kt = 0; kt < DMODEL; kt += 32) {
        __syncthreads();
#pragma unroll
        for (int i = 0; i < 4; i++) {
            const int r = lr + 32 * i;
            const float4 xa = *(const float4*)(X + (size_t)(row0 + r) * DMODEL + kt + lk);
            const float4 wa = *(const float4*)(W + (size_t)(col0 + r) * DMODEL + kt + lk);
            *(float4*)&Xs[r * 36 + lk] =
                make_float4(f2tf_f(xa.x), f2tf_f(xa.y), f2tf_f(xa.z), f2tf_f(xa.w));
            *(float4*)&Ws[r * 36 + lk] =
                make_float4(f2tf_f(wa.x), f2tf_f(wa.y), f2tf_f(wa.z), f2tf_f(wa.w));
        }
        __syncthreads();

#pragma unroll
        for (int ks = 0; ks < 4; ks++) {
            const int k = ks * 8;
            uint32_t Af[4][4];
#pragma unroll
            for (int mt = 0; mt < 4; mt++) {
                const int rb = wr + mt * 16 + (lane >> 2);
                Af[mt][0] = __float_as_uint(Xs[rb * 36 + k + (lane & 3)]);
                Af[mt][1] = __float_as_uint(Xs[(rb + 8) * 36 + k + (lane & 3)]);
                Af[mt][2] = __float_as_uint(Xs[rb * 36 + k + 4 + (lane & 3)]);
                Af[mt][3] = __float_as_uint(Xs[(rb + 8) * 36 + k + 4 + (lane & 3)]);
            }
            uint32_t Bf[4][2];
#pragma unroll
            for (int nt = 0; nt < 4; nt++) {
                const int cb = wc + nt * 8 + (lane >> 2);
                Bf[nt][0] = __float_as_uint(Ws[cb * 36 + k + (lane & 3)]);
                Bf[nt][1] = __float_as_uint(Ws[cb * 36 + k + 4 + (lane & 3)]);
            }
#pragma unroll
            for (int mt = 0; mt < 4; mt++)
#pragma unroll
                for (int nt = 0; nt < 4; nt++)
                    mma_tf32(acc[mt][nt], Af[mt], Bf[nt]);
        }
    }

    // Epilogue: bias, scale, head-split store (float2: col pairs share a head)
#pragma unroll
    for (int mt = 0; mt < 4; mt++) {
#pragma unroll
        for (int rr = 0; rr < 2; rr++) {
            const int rloc = wr + mt * 16 + (lane >> 2) + rr * 8;
            const int r = row0 + rloc;
            const int b = r >> 11;
            const int s = r & (S_LEN - 1);
#pragma unroll
            for (int nt = 0; nt < 4; nt++) {
                const int c0 = wc + nt * 8 + 2 * (lane & 3);
                const int e0 = col0 + c0;
                const int h  = e0 >> 6;
                const int dh = e0 & 63;
                float2 o;
                o.x = (acc[mt][nt][rr * 2 + 0] + bias_s[c0]) * scale;
                o.y = (acc[mt][nt][rr * 2 + 1] + bias_s[c0 + 1]) * scale;
                *(float2*)&OUT[(((size_t)b * NHEAD + h) * S_LEN + s) * DHEAD + dh] = o;
            }
        }
    }
}

// ---------------------------------------------------------------------------
// Flash attention, tf32 mma. Br=128, Bc=64, 8 warps (warp = 16-row strip).
// Smem (dynamic, 87KB): Qs[128][68], KP[128][68] (K tile then recycled as P),
// Vs[64][68] transposed ([dh][s]). ld=68 -> conflict-free fragment loads.
// ---------------------------------------------------------------------------
__global__ __launch_bounds__(256, 2) void attn_kernel(float* __restrict__ out)
{
    extern __shared__ float sm[];
    float* Qs = sm;                  // 128*68
    float* KP = sm + 128 * 68;       // 128*68 (K uses first 64 rows)
    float* Vs = KP + 128 * 68;       // 64*68, stored [dh][s]

    const int tid  = threadIdx.x;
    const int lane = tid & 31;
    const int wid  = tid >> 5;
    const int bh = blockIdx.y;
    const int qb = blockIdx.x;

    const float* __restrict__ Qg = g_Q + (size_t)bh * S_LEN * DHEAD + (size_t)qb * 128 * DHEAD;
    const float* __restrict__ Kg = g_K + (size_t)bh * S_LEN * DHEAD;
    const float* __restrict__ Vg = g_V + (size_t)bh * S_LEN * DHEAD;

    // Stage Q (tf32): 128x64
    {
        const int r = tid >> 1;
        const int c0 = (tid & 1) * 32;
#pragma unroll
        for (int j = 0; j < 8; j++) {
            const float4 v = *(const float4*)(Qg + (size_t)r * DHEAD + c0 + j * 4);
            *(float4*)&Qs[r * 68 + c0 + j * 4] =
                make_float4(f2tf_f(v.x), f2tf_f(v.y), f2tf_f(v.z), f2tf_f(v.w));
        }
    }

    float o[8][4];
    float m0 = -1e30f, m1 = -1e30f, l0 = 0.0f, l1 = 0.0f;
#pragma unroll
    for (int nt = 0; nt < 8; nt++)
#pragma unroll
        for (int j = 0; j < 4; j++) o[nt][j] = 0.0f;

    const int qrow = wid * 16 + (lane >> 2);   // this thread's row (and +8)

    for (int kt = 0; kt < S_LEN; kt += 64) {
        __syncthreads();  // prev PV readers done (also covers Q staging, iter 0)

        // Stage K [c][d] and V transposed [dh][s], both tf32
        {
            const int c  = tid >> 2;
            const int q4 = (tid & 3) * 16;
#pragma unroll
            for (int j = 0; j < 4; j++) {
                const int d0 = q4 + j * 4;
                const float4 kv = *(const float4*)(Kg + (size_t)(kt + c) * DHEAD + d0);
                *(float4*)&KP[c * 68 + d0] =
                    make_float4(f2tf_f(kv.x), f2tf_f(kv.y), f2tf_f(kv.z), f2tf_f(kv.w));
                const float4 vv = *(const float4*)(Vg + (size_t)(kt + c) * DHEAD + d0);
                Vs[(d0 + 0) * 68 + c] = f2tf_f(vv.x);
                Vs[(d0 + 1) * 68 + c] = f2tf_f(vv.y);
                Vs[(d0 + 2) * 68 + c] = f2tf_f(vv.z);
                Vs[(d0 + 3) * 68 + c] = f2tf_f(vv.w);
            }
        }
        __syncthreads();

        // S = Q K^T (scores in log2 domain; scale folded into Q)
        float s[8][4];
#pragma unroll
        for (int nt = 0; nt < 8; nt++)
#pragma unroll
            for (int j = 0; j < 4; j++) s[nt][j] = 0.0f;

#pragma unroll
        for (int ks = 0; ks < 8; ks++) {
            const int k = ks * 8;
            uint32_t Af[4];
            Af[0] = __float_as_uint(Qs[qrow * 68 + k + (lane & 3)]);
            Af[1] = __float_as_uint(Qs[(qrow + 8) * 68 + k + (lane & 3)]);
            Af[2] = __float_as_uint(Qs[qrow * 68 + k + 4 + (lane & 3)]);
            Af[3] = __float_as_uint(Qs[(qrow + 8) * 68 + k + 4 + (lane & 3)]);
#pragma unroll
            for (int nt = 0; nt < 8; nt++) {
                uint32_t Bf[2];
                const int cb = nt * 8 + (lane >> 2);
                Bf[0] = __float_as_uint(KP[cb * 68 + k + (lane & 3)]);
                Bf[1] = __float_as_uint(KP[cb * 68 + k + 4 + (lane & 3)]);
                mma_tf32(s[nt], Af, Bf);
            }
        }

        // Online softmax: thread owns rows qrow (j=0,1) and qrow+8 (j=2,3)
        float mx0 = -1e30f, mx1 = -1e30f;
#pragma unroll
        for (int nt = 0; nt < 8; nt++) {
            mx0 = fmaxf(mx0, fmaxf(s[nt][0], s[nt][1]));
            mx1 = fmaxf(mx1, fmaxf(s[nt][2], s[nt][3]));
        }
#pragma unroll
        for (int off = 1; off < 4; off <<= 1) {
            mx0 = fmaxf(mx0, __shfl_xor_sync(0xffffffffu, mx0, off));
            mx1 = fmaxf(mx1, __shfl_xor_sync(0xffffffffu, mx1, off));
        }
        const float nm0 = fmaxf(m0, mx0), nm1 = fmaxf(m1, mx1);
        const float corr0 = fast_exp2(m0 - nm0), corr1 = fast_exp2(m1 - nm1);
        m0 = nm0; m1 = nm1;

        float rs0 = 0.0f, rs1 = 0.0f;
#pragma unroll
        for (int nt = 0; nt < 8; nt++) {
            s[nt][0] = fast_exp2(s[nt][0] - m0);
            s[nt][1] = fast_exp2(s[nt][1] - m0);
            s[nt][2] = fast_exp2(s[nt][2] - m1);
            s[nt][3] = fast_exp2(s[nt][3] - m1);
            rs0 += s[nt][0] + s[nt][1];
            rs1 += s[nt][2] + s[nt][3];
        }
#pragma unroll
        for (int off = 1; off < 4; off <<= 1) {
            rs0 += __shfl_xor_sync(0xffffffffu, rs0, off);
            rs1 += __shfl_xor_sync(0xffffffffu, rs1, off);
        }
        l0 = l0 * corr0 + rs0;
        l1 = l1 * corr1 + rs1;

        __syncthreads();  // all warps done reading KP as K

        // Write P (tf32) into KP[r][k]
#pragma unroll
        for (int nt = 0; nt < 8; nt++) {
            const int c = nt * 8 + 2 * (lane & 3);
            *(float2*)&KP[qrow * 68 + c]       = make_float2(f2tf_f(s[nt][0]), f2tf_f(s[nt][1]));
            *(float2*)&KP[(qrow + 8) * 68 + c] = make_float2(f2tf_f(s[nt][2]), f2tf_f(s[nt][3]));
        }
        __syncthreads();

        // Rescale O, then O += P V
#pragma unroll
        for (int nt = 0; nt < 8; nt++) {
            o[nt][0] *= corr0; o[nt][1] *= corr0;
            o[nt][2] *= corr1; o[nt][3] *= corr1;
        }
#pragma unroll
        for (int ks = 0; ks < 8; ks++) {
            const int k = ks * 8;
            uint32_t Af[4];
            Af[0] = __float_as_uint(KP[qrow * 68 + k + (lane & 3)]);
            Af[1] = __float_as_uint(KP[(qrow + 8) * 68 + k + (lane & 3)]);
            Af[2] = __float_as_uint(KP[qrow * 68 + k + 4 + (lane & 3)]);
            Af[3] = __float_as_uint(KP[(qrow + 8) * 68 + k + 4 + (lane & 3)]);
#pragma unroll
            for (int nt = 0; nt < 8; nt++) {
                uint32_t Bf[2];
                const int nb = nt * 8 + (lane >> 2);          // dh
                Bf[0] = __float_as_uint(Vs[nb * 68 + k + (lane & 3)]);
                Bf[1] = __float_as_uint(Vs[nb * 68 + k + 4 + (lane & 3)]);
                mma_tf32(o[nt], Af, Bf);
            }
        }
    }

    // Epilogue: out[b, (s*64+dh)*16 + h]
    const int b = bh >> 4;
    const int h = bh & 15;
    float* outb = out + (size_t)b * (S_LEN * DMODEL) + h;
    const float il0 = 1.0f / l0, il1 = 1.0f / l1;
    const int sg0 = qb * 128 + qrow;
#pragma unroll
    for (int nt = 0; nt < 8; nt++) {
        const int dh = nt * 8 + 2 * (lane & 3);
        outb[(size_t)(sg0 * DHEAD + dh) * NHEAD]           = o[nt][0] * il0;
        outb[(size_t)(sg0 * DHEAD + dh + 1) * NHEAD]       = o[nt][1] * il0;
        outb[(size_t)((sg0 + 8) * DHEAD + dh) * NHEAD]     = o[nt][2] * il1;
        outb[(size_t)((sg0 + 8) * DHEAD + dh + 1) * NHEAD] = o[nt][3] * il1;
    }
}

#define ATTN_SMEM_BYTES ((128 * 68 * 2 + 64 * 68) * 4)

extern "C" void kernel_launch(void* const* d_in, const int* in_sizes, int n_in,
                              void* d_out, int out_size)
{
    (void)in_sizes; (void)n_in; (void)out_size;
    const float* q   = (const float*)d_in[0];
    const float* k   = (const float*)d_in[1];
    const float* v   = (const float*)d_in[2];
    const float* inv = (const float*)d_in[4];
    const float* Wq  = (const float*)d_in[5];
    const float* bq  = (const float*)d_in[6];
    const float* Wk  = (const float*)d_in[7];
    const float* bk  = (const float*)d_in[8];
    const float* Wv  = (const float*)d_in[9];
    const float* bv  = (const float*)d_in[10];

    cudaFuncSetAttribute(attn_kernel, cudaFuncAttributeMaxDynamicSharedMemorySize,
                         ATTN_SMEM_BYTES);

    dim3 gproj(DMODEL / 128, NROWS / 128, 3);   // (8, 32, 3)
    proj_kernel<<<gproj, 256>>>(q, k, v, Wq, Wk, Wv, bq, bk, bv, inv);

    dim3 gattn(S_LEN / 128, BATCH * NHEAD);     // (16, 32)
    attn_kernel<<<gattn, 256, ATTN_SMEM_BYTES>>>((float*)d_out);
}